// round 14
// baseline (speedup 1.0000x reference)
#include <cuda_runtime.h>

// ArnoldCat ^7, n=1024: out[a,b] <- in[(239a+169b)&1023, (338a+239b)&1023].
//
// Lattice basis: (a,b) = (169k', j'-239k'), source = (169j', k'+239j').
// Tile (m,n): k'=32m+k, j'=32n+j, k,j in [0,32). Exact partition of both input
// and output rows (no overlap, no duplicate traffic).
//   Phase 1: row j -> source row 169j'&1023, 96 consecutive floats at
//            3*((32m+239j')&1023). Element f=3k+c -> osm[99k + c + 3j].
//   Phase 2: output row a=169k'&1023, 96 consecutive floats at
//            3*((32n-239k')&1023); float f=3j+c read from osm[99k + f].
// Stride 99 ≡ 3 (mod 32): STS and LDS addr ≡ lane + const (mod 32), conflict-free.
//
// R14 vs R11 (single change): phase-2 address chains (output row, window base,
// wrap predicate) are hoisted ABOVE __syncthreads into the LDG latency shadow;
// post-barrier work is pure LDS -> STG. Cache policy: __ldg reads (best
// measured kernel time), __stcs writes.

static constexpr unsigned THREADS = 256u;
static constexpr unsigned BLOCKS  = 16u * 32u * 32u;   // batch x m x n
static constexpr unsigned IMG_F   = 1024u * 3072u;

__global__ void __launch_bounds__(THREADS)
arnold_v14_kernel(const float* __restrict__ in, float* __restrict__ out) {
    __shared__ float osm[3168];                        // 32 x 99 floats = 12672 B

    const unsigned id    = blockIdx.x;
    const unsigned n     = id & 31u;
    const unsigned m     = (id >> 5) & 31u;
    const unsigned batch = id >> 10;
    const unsigned lane  = threadIdx.x & 31u;
    const unsigned warp  = threadIdx.x >> 5;           // 0..7

    const float* inb = in + batch * IMG_F;

    // per-(lane,t) invariant: element f = lane+32t -> smem base 99*(f/3) + f%3
    unsigned sb[3];
    #pragma unroll
    for (unsigned t = 0; t < 3u; ++t) {
        unsigned f = lane + 32u * t;
        unsigned k = f / 3u;
        sb[t] = 99u * k + (f - 3u * k);
    }

    // ---- Phase 1: batched exact gather (12 independent LDGs) ----
    float v[4][3];
    #pragma unroll
    for (unsigned r = 0; r < 4u; ++r) {
        unsigned j   = warp + 8u * r;
        unsigned jp  = 32u * n + j;
        unsigned ry  = (169u * jp) & 1023u;
        unsigned cb3 = ((32u * m + 239u * jp) & 1023u) * 3u;
        const float* rowp = inb + ry * 3072u;
        if (cb3 <= 3072u - 96u) {                      // warp-uniform fast path
            const float* seg = rowp + cb3 + lane;
            v[r][0] = __ldg(seg);
            v[r][1] = __ldg(seg + 32u);
            v[r][2] = __ldg(seg + 64u);
        } else {                                       // row wraps (rare)
            #pragma unroll
            for (unsigned t = 0; t < 3u; ++t) {
                unsigned o = cb3 + lane + 32u * t;
                if (o >= 3072u) o -= 3072u;
                v[r][t] = __ldg(rowp + o);
            }
        }
    }

    // ---- Hoisted phase-2 addressing (smem-independent; hides in LDG shadow) ----
    float*   outb = out + batch * IMG_F;
    float*   oseg[4];                                  // per-row write base (+lane)
    unsigned ob3v[4];
    bool     fastp[4];
    #pragma unroll
    for (unsigned it = 0; it < 4u; ++it) {
        unsigned k   = warp + 8u * it;
        unsigned kp  = 32u * m + k;
        unsigned a   = (169u * kp) & 1023u;
        unsigned ob3 = ((32u * n - 239u * kp) & 1023u) * 3u;
        ob3v[it]  = ob3;
        fastp[it] = (ob3 <= 3072u - 96u);
        oseg[it]  = outb + a * 3072u + ob3 + lane;     // valid for fast path
    }

    // ---- STS (conflict-free), then barrier ----
    #pragma unroll
    for (unsigned r = 0; r < 4u; ++r) {
        unsigned j3 = 3u * (warp + 8u * r);
        #pragma unroll
        for (unsigned t = 0; t < 3u; ++t)
            osm[sb[t] + j3] = v[r][t];
    }
    __syncthreads();

    // ---- Phase 2: pure LDS -> STG ----
    #pragma unroll
    for (unsigned it = 0; it < 4u; ++it) {
        unsigned k = warp + 8u * it;
        const float* sr = osm + 99u * k + lane;        // base + immediate offsets
        float r0 = sr[0], r1 = sr[32], r2 = sr[64];
        if (fastp[it]) {                               // warp-uniform branch
            float* seg = oseg[it];
            __stcs(seg,       r0);
            __stcs(seg + 32u, r1);
            __stcs(seg + 64u, r2);
        } else {                                       // row wraps (rare)
            float* orow = oseg[it] - ob3v[it] - lane;  // recover row base
            float rr[3] = {r0, r1, r2};
            #pragma unroll
            for (unsigned t = 0; t < 3u; ++t) {
                unsigned o = ob3v[it] + lane + 32u * t;
                if (o >= 3072u) o -= 3072u;
                __stcs(orow + o, rr[t]);
            }
        }
    }
}

extern "C" void kernel_launch(void* const* d_in, const int* in_sizes, int n_in,
                              void* d_out, int out_size) {
    (void)in_sizes; (void)n_in; (void)out_size;
    arnold_v14_kernel<<<BLOCKS, THREADS>>>((const float*)d_in[0], (float*)d_out);
}

// round 15
// speedup vs baseline: 1.0221x; 1.0221x over previous
#include <cuda_runtime.h>

// ArnoldCat ^7, n=1024: out[a,b] <- in[(239a+169b)&1023, (338a+239b)&1023].
//
// Lattice basis: (a,b) = (169k', j'-239k'), source = (169j', k'+239j').
// Tile (m,n): k'=32m+k, j'=32n+j, k,j in [0,32). Exact partition of both input
// and output rows (no overlap, no duplicate traffic).
//   Phase 1: row j -> source row 169j'&1023, 96 consecutive floats at
//            3*((32m+239j')&1023). Element f=3k+c -> osm[99k + c + 3j].
//   Phase 2: output row a=169k'&1023, 96 consecutive floats at
//            3*((32n-239k')&1023); float f=3j+c read from osm[99k + f].
// Stride 99 ≡ 3 (mod 32): STS and LDS addr ≡ lane + const (mod 32), conflict-free.
//
// R15 vs R11 (single change): block id decoded in 4x4 Morton groups over (m,n):
//   id = [batch(4)][mh(3)][nh(3)][ml(2)][nl(2)]
// The ~16 co-resident blocks of a group touch each source row AND each output
// row in 4 adjacent 384B segments (1536B effective bursts on BOTH streams),
// letting the DRAM scheduler merge requests. Zero cost elsewhere.

static constexpr unsigned THREADS = 256u;
static constexpr unsigned BLOCKS  = 16u * 32u * 32u;   // batch x m x n
static constexpr unsigned IMG_F   = 1024u * 3072u;

__global__ void __launch_bounds__(THREADS)
arnold_v15_kernel(const float* __restrict__ in, float* __restrict__ out) {
    __shared__ float osm[3168];                        // 32 x 99 floats = 12672 B

    const unsigned id    = blockIdx.x;
    const unsigned nl    = id & 3u;
    const unsigned ml    = (id >> 2) & 3u;
    const unsigned nh    = (id >> 4) & 7u;
    const unsigned mh    = (id >> 7) & 7u;
    const unsigned batch = id >> 10;
    const unsigned m     = (mh << 2) | ml;
    const unsigned n     = (nh << 2) | nl;
    const unsigned lane  = threadIdx.x & 31u;
    const unsigned warp  = threadIdx.x >> 5;           // 0..7

    const float* inb = in + batch * IMG_F;

    // per-(lane,t) invariant: element f = lane+32t -> smem base 99*(f/3) + f%3
    unsigned sb[3];
    #pragma unroll
    for (unsigned t = 0; t < 3u; ++t) {
        unsigned f = lane + 32u * t;
        unsigned k = f / 3u;
        sb[t] = 99u * k + (f - 3u * k);
    }

    // ---- Phase 1: batched exact gather (12 independent LDGs) ----
    float v[4][3];
    #pragma unroll
    for (unsigned r = 0; r < 4u; ++r) {
        unsigned j   = warp + 8u * r;
        unsigned jp  = 32u * n + j;
        unsigned ry  = (169u * jp) & 1023u;
        unsigned cb3 = ((32u * m + 239u * jp) & 1023u) * 3u;
        const float* rowp = inb + ry * 3072u;
        if (cb3 <= 3072u - 96u) {                      // warp-uniform fast path
            const float* seg = rowp + cb3 + lane;
            v[r][0] = __ldg(seg);
            v[r][1] = __ldg(seg + 32u);
            v[r][2] = __ldg(seg + 64u);
        } else {                                       // row wraps (rare)
            #pragma unroll
            for (unsigned t = 0; t < 3u; ++t) {
                unsigned o = cb3 + lane + 32u * t;
                if (o >= 3072u) o -= 3072u;
                v[r][t] = __ldg(rowp + o);
            }
        }
    }
    #pragma unroll
    for (unsigned r = 0; r < 4u; ++r) {                // conflict-free STS
        unsigned j3 = 3u * (warp + 8u * r);
        #pragma unroll
        for (unsigned t = 0; t < 3u; ++t)
            osm[sb[t] + j3] = v[r][t];
    }
    __syncthreads();

    // ---- Phase 2: exact scatter, contiguous smem rows, streaming writes ----
    float* outb = out + batch * IMG_F;
    #pragma unroll
    for (unsigned it = 0; it < 4u; ++it) {
        unsigned k   = warp + 8u * it;
        unsigned kp  = 32u * m + k;
        unsigned a   = (169u * kp) & 1023u;
        unsigned ob3 = ((32u * n - 239u * kp) & 1023u) * 3u;
        const float* sr = osm + 99u * k + lane;        // base + immediate offsets
        float r0 = sr[0], r1 = sr[32], r2 = sr[64];
        float* orow = outb + a * 3072u;
        if (ob3 <= 3072u - 96u) {                      // warp-uniform fast path
            float* seg = orow + ob3 + lane;
            __stcs(seg,       r0);
            __stcs(seg + 32u, r1);
            __stcs(seg + 64u, r2);
        } else {                                       // row wraps (rare)
            float rr[3] = {r0, r1, r2};
            #pragma unroll
            for (unsigned t = 0; t < 3u; ++t) {
                unsigned o = ob3 + lane + 32u * t;
                if (o >= 3072u) o -= 3072u;
                __stcs(orow + o, rr[t]);
            }
        }
    }
}

extern "C" void kernel_launch(void* const* d_in, const int* in_sizes, int n_in,
                              void* d_out, int out_size) {
    (void)in_sizes; (void)n_in; (void)out_size;
    arnold_v15_kernel<<<BLOCKS, THREADS>>>((const float*)d_in[0], (float*)d_out);
}